// round 3
// baseline (speedup 1.0000x reference)
#include <cuda_runtime.h>
#include <math.h>

// ---------------------------------------------------------------------------
// PADigitalTwin: 5-tap Volterra memory polynomial (orders 1,3,5,7) + global
// noise-floor calibration + phase-noise rotation + AWGN.
//
//   x           [16, 131072, 2] f32
//   coeffs_real [4, 5]          f32
//   coeffs_imag [4, 5]          f32
//   awgn        [16, 131068, 2] f32
//   phase_noise [16, 131068]    f32
//   out         [16, 131068, 2] f32
//
// pa_main: Volterra once -> g_y scratch (L2) + power partials + last-block
//          reduction to noise_std (deterministic fixed-order sum).
// pa_epi:  streaming rotate + AWGN epilogue.
// ---------------------------------------------------------------------------

#define MEMD      5
#define SLEN      131072
#define OUTLEN    131068          // SLEN - MEMD + 1
#define BATCH     16
#define TPT       4               // outputs per thread
#define JOBS_PB   (OUTLEN / TPT)  // 32767 (exact)
#define BLOCK     256
#define GRIDX     ((JOBS_PB + BLOCK - 1) / BLOCK)   // 128
#define NPART     (GRIDX * BATCH)                   // 2048

__device__ float        g_y[(size_t)BATCH * OUTLEN * 2];  // 16.8 MB (L2-resident)
__device__ float        g_partials[NPART];
__device__ float        g_noise_std;
__device__ unsigned int g_done;                           // zero-init; self-resets

// ---------------- Pass 1: Volterra + fused global reduction -----------------
__global__ __launch_bounds__(BLOCK)
void pa_main(const float* __restrict__ x,
             const float* __restrict__ crg,
             const float* __restrict__ cig)
{
    __shared__ float scr[20], sci[20];          // [k*5+m]
    if (threadIdx.x < 20) {
        scr[threadIdx.x] = __ldg(&crg[threadIdx.x]);
        sci[threadIdx.x] = __ldg(&cig[threadIdx.x]);
    }
    __syncthreads();

    const int j = blockIdx.x * BLOCK + threadIdx.x;
    const int b = blockIdx.y;
    float acc = 0.f;

    if (j < JOBS_PB) {
        const float4* xb4 = (const float4*)(x + (size_t)b * SLEN * 2);
        float I[8], Q[8], a2[8];
#pragma unroll
        for (int v = 0; v < 4; v++) {
            float4 p = __ldg(&xb4[j * 2 + v]);   // two complex samples / float4
            I[2 * v]     = p.x;  Q[2 * v]     = p.y;
            I[2 * v + 1] = p.z;  Q[2 * v + 1] = p.w;
        }
#pragma unroll
        for (int s = 0; s < 8; s++)
            a2[s] = fmaf(I[s], I[s], Q[s] * Q[s]);

        float yr[TPT], yi[TPT];
#pragma unroll
        for (int o = 0; o < TPT; o++) { yr[o] = 0.f; yi[o] = 0.f; }

        // m-outer: 8 coefficients live at a time (one LDS each, broadcast)
#pragma unroll
        for (int m = 0; m < MEMD; m++) {
            const float cr0 = scr[m],      ci0 = sci[m];
            const float cr1 = scr[5 + m],  ci1 = sci[5 + m];
            const float cr2 = scr[10 + m], ci2 = sci[10 + m];
            const float cr3 = scr[15 + m], ci3 = sci[15 + m];
#pragma unroll
            for (int o = 0; o < TPT; o++) {
                const int w = o + (MEMD - 1) - m;
                const float e = a2[w];
                const float fr = fmaf(fmaf(fmaf(cr3, e, cr2), e, cr1), e, cr0);
                const float fi = fmaf(fmaf(fmaf(ci3, e, ci2), e, ci1), e, ci0);
                yr[o] = fmaf(fr, I[w], fmaf(-fi, Q[w], yr[o]));
                yi[o] = fmaf(fr, Q[w], fmaf( fi, I[w], yi[o]));
            }
        }

#pragma unroll
        for (int o = 0; o < TPT; o++)
            acc = fmaf(yr[o], yr[o], fmaf(yi[o], yi[o], acc));

        float4* y4 = (float4*)(g_y + (size_t)b * OUTLEN * 2);
        float4 s0, s1;
        s0.x = yr[0]; s0.y = yi[0]; s0.z = yr[1]; s0.w = yi[1];
        s1.x = yr[2]; s1.y = yi[2]; s1.z = yr[3]; s1.w = yi[3];
        y4[j * 2]     = s0;
        y4[j * 2 + 1] = s1;
    }

    // deterministic block reduction -> g_partials
    __shared__ float shr[BLOCK / 32];
#pragma unroll
    for (int off = 16; off > 0; off >>= 1)
        acc += __shfl_down_sync(0xffffffffu, acc, off);
    if ((threadIdx.x & 31) == 0) shr[threadIdx.x >> 5] = acc;
    __syncthreads();
    if (threadIdx.x < BLOCK / 32) {
        float v = shr[threadIdx.x];
#pragma unroll
        for (int off = (BLOCK / 32) / 2; off > 0; off >>= 1)
            v += __shfl_down_sync(0xffu, v, off);
        if (threadIdx.x == 0)
            g_partials[blockIdx.y * GRIDX + blockIdx.x] = v;
    }

    // last-block final reduction (deterministic: fixed assignment + tree)
    __shared__ bool s_last;
    __threadfence();
    if (threadIdx.x == 0) {
        unsigned t = atomicAdd(&g_done, 1u);
        s_last = (t == (unsigned)(NPART - 1));
    }
    __syncthreads();
    if (s_last) {
        __shared__ double shd[BLOCK];
        double s = 0.0;
#pragma unroll
        for (int i = 0; i < NPART / BLOCK; i++)
            s += (double)g_partials[threadIdx.x + i * BLOCK];
        shd[threadIdx.x] = s;
        __syncthreads();
#pragma unroll
        for (int off = BLOCK / 2; off > 0; off >>= 1) {
            if (threadIdx.x < off) shd[threadIdx.x] += shd[threadIdx.x + off];
            __syncthreads();
        }
        if (threadIdx.x == 0) {
            double mean = shd[0] / ((double)BATCH * (double)OUTLEN);
            g_noise_std = (float)sqrt(mean * 0.5 * 1.0e-6);   // 10^(-60/10)
            g_done = 0u;                                      // reset for replay
        }
    }
}

// ---------------- Pass 2: streaming epilogue --------------------------------
__global__ __launch_bounds__(BLOCK)
void pa_epi(const float* __restrict__ awgn,
            const float* __restrict__ pn,
            float* __restrict__ out)
{
    const int j = blockIdx.x * BLOCK + threadIdx.x;
    if (j >= JOBS_PB) return;
    const int b = blockIdx.y;

    const float4* y4  = (const float4*)(g_y  + (size_t)b * OUTLEN * 2);
    const float4* aw4 = (const float4*)(awgn + (size_t)b * OUTLEN * 2);
    const float4* pn4 = (const float4*)(pn   + (size_t)b * OUTLEN);

    float4 s0 = y4[j * 2];
    float4 s1 = y4[j * 2 + 1];
    float4 p  = __ldg(&pn4[j]);
    float4 a0 = __ldg(&aw4[j * 2]);
    float4 a1 = __ldg(&aw4[j * 2 + 1]);
    const float ns = g_noise_std;

    const float KRAD = 0.008726646259971648f;   // 0.5 * pi / 180
    float c0, sn0, c1, sn1, c2, sn2, c3, sn3;
    __sincosf(p.x * KRAD, &sn0, &c0);
    __sincosf(p.y * KRAD, &sn1, &c1);
    __sincosf(p.z * KRAD, &sn2, &c2);
    __sincosf(p.w * KRAD, &sn3, &c3);

    float4 o0, o1;
    o0.x = fmaf(a0.x, ns, s0.x * c0 - s0.y * sn0);
    o0.y = fmaf(a0.y, ns, s0.x * sn0 + s0.y * c0);
    o0.z = fmaf(a0.z, ns, s0.z * c1 - s0.w * sn1);
    o0.w = fmaf(a0.w, ns, s0.z * sn1 + s0.w * c1);
    o1.x = fmaf(a1.x, ns, s1.x * c2 - s1.y * sn2);
    o1.y = fmaf(a1.y, ns, s1.x * sn2 + s1.y * c2);
    o1.z = fmaf(a1.z, ns, s1.z * c3 - s1.w * sn3);
    o1.w = fmaf(a1.w, ns, s1.z * sn3 + s1.w * c3);

    float4* out4 = (float4*)(out + (size_t)b * OUTLEN * 2);
    out4[j * 2]     = o0;
    out4[j * 2 + 1] = o1;
}

// ---------------------------------------------------------------------------
extern "C" void kernel_launch(void* const* d_in, const int* in_sizes, int n_in,
                              void* d_out, int out_size)
{
    const float* x    = (const float*)d_in[0];
    const float* cr   = (const float*)d_in[1];
    const float* ci   = (const float*)d_in[2];
    const float* awgn = (const float*)d_in[3];
    const float* pn   = (const float*)d_in[4];
    float* out        = (float*)d_out;

    dim3 grid(GRIDX, BATCH);
    pa_main<<<grid, BLOCK>>>(x, cr, ci);
    pa_epi<<<grid, BLOCK>>>(awgn, pn, out);
}